// round 1
// baseline (speedup 1.0000x reference)
#include <cuda_runtime.h>
#include <cuda_bf16.h>

// Joiner: out[b,t,u,v] = tanh(src[b,t,:] + tgt[b,u,:]) . W[v,:] + bias[v]
// Treated as GEMM: M = B*T*U = 160000, K = D = 512, N = V = 1024.
// A[m,k] = tanh(src[b,t,k] + tgt[b,u,k]) generated on the fly per tile.
//
// Round 0: correct fp32 SIMT baseline, 128x128x16 tiling, 8x8 per thread.

constexpr int Bb = 4;
constexpr int Tt = 400;
constexpr int Uu = 100;
constexpr int Dd = 512;
constexpr int Vv = 1024;
constexpr int Mm = Bb * Tt * Uu;   // 160000 = 128 * 1250

#define BM 128
#define BN 128
#define BK 16
#define TM 8
#define TN 8

__global__ __launch_bounds__(256, 2)
void joiner_gemm_kernel(const float* __restrict__ src,
                        const float* __restrict__ tgt,
                        const float* __restrict__ W,
                        const float* __restrict__ bias,
                        float* __restrict__ out) {
    __shared__ float As[BK][BM];   // A tile, transposed: As[k][m]
    __shared__ float Bs[BK][BN];   // W tile, transposed: Bs[k][n]

    const int tid = threadIdx.x;
    const int m0 = blockIdx.x * BM;
    const int n0 = blockIdx.y * BN;

    // Output thread tile: 16x16 threads, each 8x8 outputs
    const int trow = tid >> 4;    // 0..15 (m direction)
    const int tcol = tid & 15;    // 0..15 (n direction)

    // Load assignment: each thread loads 2 float4 for A and 2 float4 for W.
    // row = tid/4 (0..63, +64 on second iter), col4 = (tid%4)*4.
    const int ld_row = tid >> 2;         // 0..63
    const int ld_col = (tid & 3) * 4;    // 0,4,8,12

    // Precompute src/tgt row base pointers for this thread's two A rows
    const float* s_ptr[2];
    const float* t_ptr[2];
#pragma unroll
    for (int i = 0; i < 2; i++) {
        int m = m0 + ld_row + i * 64;
        int b = m / (Tt * Uu);
        int r = m - b * (Tt * Uu);
        int t = r / Uu;
        int u = r - t * Uu;
        s_ptr[i] = src + ((size_t)b * Tt + t) * Dd;
        t_ptr[i] = tgt + ((size_t)b * Uu + u) * Dd;
    }

    float acc[TM][TN];
#pragma unroll
    for (int i = 0; i < TM; i++)
#pragma unroll
        for (int j = 0; j < TN; j++) acc[i][j] = 0.0f;

    for (int k0 = 0; k0 < Dd; k0 += BK) {
        // ---- A tile: tanh(src + tgt), store transposed As[k][m] ----
#pragma unroll
        for (int i = 0; i < 2; i++) {
            float4 s4 = *reinterpret_cast<const float4*>(s_ptr[i] + k0 + ld_col);
            float4 t4 = *reinterpret_cast<const float4*>(t_ptr[i] + k0 + ld_col);
            int mm = ld_row + i * 64;
            As[ld_col + 0][mm] = tanhf(s4.x + t4.x);
            As[ld_col + 1][mm] = tanhf(s4.y + t4.y);
            As[ld_col + 2][mm] = tanhf(s4.z + t4.z);
            As[ld_col + 3][mm] = tanhf(s4.w + t4.w);
        }
        // ---- W tile: Bs[k][n] = W[n0+n][k0+k] ----
#pragma unroll
        for (int i = 0; i < 2; i++) {
            int vv = ld_row + i * 64;
            float4 w4 = *reinterpret_cast<const float4*>(
                W + (size_t)(n0 + vv) * Dd + k0 + ld_col);
            Bs[ld_col + 0][vv] = w4.x;
            Bs[ld_col + 1][vv] = w4.y;
            Bs[ld_col + 2][vv] = w4.z;
            Bs[ld_col + 3][vv] = w4.w;
        }
        __syncthreads();

#pragma unroll
        for (int k = 0; k < BK; k++) {
            float4 a0 = *reinterpret_cast<const float4*>(&As[k][trow * TM]);
            float4 a1 = *reinterpret_cast<const float4*>(&As[k][trow * TM + 4]);
            float4 b0 = *reinterpret_cast<const float4*>(&Bs[k][tcol * TN]);
            float4 b1 = *reinterpret_cast<const float4*>(&Bs[k][tcol * TN + 4]);
            float af[TM] = {a0.x, a0.y, a0.z, a0.w, a1.x, a1.y, a1.z, a1.w};
            float bf[TN] = {b0.x, b0.y, b0.z, b0.w, b1.x, b1.y, b1.z, b1.w};
#pragma unroll
            for (int i = 0; i < TM; i++)
#pragma unroll
                for (int j = 0; j < TN; j++)
                    acc[i][j] = fmaf(af[i], bf[j], acc[i][j]);
        }
        __syncthreads();
    }

    // ---- Epilogue: add bias, store float4 ----
    float4 bias0 = *reinterpret_cast<const float4*>(bias + n0 + tcol * TN);
    float4 bias1 = *reinterpret_cast<const float4*>(bias + n0 + tcol * TN + 4);
#pragma unroll
    for (int i = 0; i < TM; i++) {
        size_t m = (size_t)(m0 + trow * TM + i);
        float* orow = out + m * Vv + n0 + tcol * TN;
        float4 o0, o1;
        o0.x = acc[i][0] + bias0.x;
        o0.y = acc[i][1] + bias0.y;
        o0.z = acc[i][2] + bias0.z;
        o0.w = acc[i][3] + bias0.w;
        o1.x = acc[i][4] + bias1.x;
        o1.y = acc[i][5] + bias1.y;
        o1.z = acc[i][6] + bias1.z;
        o1.w = acc[i][7] + bias1.w;
        *reinterpret_cast<float4*>(orow) = o0;
        *reinterpret_cast<float4*>(orow + 4) = o1;
    }
}

// Defensive tail: if the harness packs the tuple (output, source_lengths,
// target_lengths) into one float buffer, append the lengths cast to float.
__global__ void joiner_tail_kernel(const int* __restrict__ src_len,
                                   const int* __restrict__ tgt_len,
                                   float* __restrict__ out,
                                   int extras) {
    int i = threadIdx.x;
    if (i < extras) {
        size_t base = (size_t)Mm * Vv;
        if (i < Bb) out[base + i] = (float)src_len[i];
        else if (i < 2 * Bb) out[base + i] = (float)tgt_len[i - Bb];
        else out[base + i] = 0.0f;
    }
}

extern "C" void kernel_launch(void* const* d_in, const int* in_sizes, int n_in,
                              void* d_out, int out_size) {
    const float* src     = (const float*)d_in[0];   // (B,T,D)
    const int*   src_len = (const int*)d_in[1];     // (B,)
    const float* tgt     = (const float*)d_in[2];   // (B,U,D)
    const int*   tgt_len = (const int*)d_in[3];     // (B,)
    const float* W       = (const float*)d_in[4];   // (V,D)
    const float* bias    = (const float*)d_in[5];   // (V,)
    float* out = (float*)d_out;

    dim3 grid(Mm / BM, Vv / BN);   // 1250 x 8
    joiner_gemm_kernel<<<grid, 256>>>(src, tgt, W, bias, out);

    long long extras = (long long)out_size - (long long)Mm * Vv;
    if (extras > 0) {
        int e = (int)(extras > 64 ? 64 : extras);
        joiner_tail_kernel<<<1, 64>>>(src_len, tgt_len, out, e);
    }
}

// round 4
// speedup vs baseline: 2.7031x; 2.7031x over previous
#include <cuda_runtime.h>
#include <cstdint>

// RNN-T Joiner as fused TF32 mma.sync GEMM (baseline-PTX tensor path; the
// toolchain lowers via compute_103 so tcgen05/sm_103a-only PTX is unavailable).
// out[m, v] = tanh(src[b,t,:] + tgt[b,u,:]) . W[v,:] + bias[v]
// M = 160000, K = 512, N = 1024.
// CTA tile 128x128, k-chunk 16, double-buffered SMEM, 8 warps of 64x32,
// mma.sync.m16n8k8 tf32 with rna rounding on both operands.

constexpr int Bb = 4, Tt = 400, Uu = 100, Dd = 512, Vv = 1024;
constexpr long long Mm = (long long)Bb * Tt * Uu;   // 160000 = 128*1250

#define BM 128
#define BN 128
#define BK 16
#define BMP 136   // A smem row stride (floats): (8c+g)%32 distinct -> conflict-free
#define BKP 20    // B smem row stride (floats): (20g+c)%32 distinct -> conflict-free
#define NCH (Dd / BK)   // 32 chunks

__device__ __forceinline__ float fast_tanh(float x) {
    float y; asm("tanh.approx.f32 %0, %1;" : "=f"(y) : "f"(x)); return y;
}
__device__ __forceinline__ float to_tf32(float x) {
    float y; asm("cvt.rna.tf32.f32 %0, %1;" : "=f"(y) : "f"(x)); return y;
}

__device__ __forceinline__ void mma_tf32(float* d, const uint32_t* a,
                                         uint32_t b0, uint32_t b1) {
    asm volatile(
        "mma.sync.aligned.m16n8k8.row.col.f32.tf32.tf32.f32 "
        "{%0,%1,%2,%3}, {%4,%5,%6,%7}, {%8,%9}, {%0,%1,%2,%3};"
        : "+f"(d[0]), "+f"(d[1]), "+f"(d[2]), "+f"(d[3])
        : "r"(a[0]), "r"(a[1]), "r"(a[2]), "r"(a[3]), "r"(b0), "r"(b1));
}

__global__ __launch_bounds__(256, 2)
void joiner_mma_kernel(const float* __restrict__ src, const float* __restrict__ tgt,
                       const float* __restrict__ W, const float* __restrict__ bias,
                       float* __restrict__ out) {
    __shared__ float As[2][BK][BMP];   // [k][m], tf32-rounded tanh values
    __shared__ float Bs[2][BN][BKP];   // [n][k], raw W (cvt at consume)

    const int tid = threadIdx.x;
    const int wid = tid >> 5, lid = tid & 31;
    const int g = lid >> 2, c = lid & 3;       // mma lane coords
    const int wm = wid >> 2, wn = wid & 3;     // warp grid 2(m) x 4(n)
    const long long m0 = (long long)blockIdx.x * BM;
    const int n0 = blockIdx.y * BN;

    // Producer mapping: 2 threads per row; thread covers 8 k per chunk.
    const int r = tid >> 1;     // 0..127 (A row within tile / W row within tile)
    const int h = tid & 1;      // k-half (0: k..k+7 low 8? -> h*8 offset)

    const float* sp;
    const float* tp;
    {
        long long m = m0 + r;
        int b = (int)(m / (Tt * Uu));
        int rem = (int)(m - (long long)b * (Tt * Uu));
        int t = rem / Uu;
        int u = rem - t * Uu;
        sp = src + ((size_t)b * Tt + t) * Dd + h * 8;
        tp = tgt + ((size_t)b * Uu + u) * Dd + h * 8;
    }
    const float* wp = W + (size_t)(n0 + r) * Dd + h * 8;
    const uint32_t bs_dst0 = (uint32_t)__cvta_generic_to_shared(&Bs[0][r][h * 8]);
    const uint32_t bs_dst1 = (uint32_t)__cvta_generic_to_shared(&Bs[1][r][h * 8]);

    float acc[4][4][4];
#pragma unroll
    for (int mt = 0; mt < 4; mt++)
#pragma unroll
        for (int nt = 0; nt < 4; nt++)
#pragma unroll
            for (int i = 0; i < 4; i++) acc[mt][nt][i] = 0.0f;

    // ---- prologue: stage A(0) in regs, cp.async B(0) -> buf0 ----
    float4 as0 = *reinterpret_cast<const float4*>(sp);
    float4 as1 = *reinterpret_cast<const float4*>(sp + 4);
    float4 at0 = *reinterpret_cast<const float4*>(tp);
    float4 at1 = *reinterpret_cast<const float4*>(tp + 4);
    asm volatile(
        "cp.async.cg.shared.global [%0], [%1], 16;\n"
        "cp.async.cg.shared.global [%2], [%3], 16;\n"
        "cp.async.commit_group;"
        :: "r"(bs_dst0), "l"(wp), "r"(bs_dst0 + 16), "l"(wp + 4) : "memory");

#pragma unroll 2
    for (int ch = 0; ch < NCH; ch++) {
        const int s = ch & 1;

        // ---- STS A chunk ch: tanh + tf32 round ----
        {
            float v[8];
            v[0] = as0.x; v[1] = as0.y; v[2] = as0.z; v[3] = as0.w;
            v[4] = as1.x; v[5] = as1.y; v[6] = as1.z; v[7] = as1.w;
            float u[8];
            u[0] = at0.x; u[1] = at0.y; u[2] = at0.z; u[3] = at0.w;
            u[4] = at1.x; u[5] = at1.y; u[6] = at1.z; u[7] = at1.w;
#pragma unroll
            for (int i = 0; i < 8; i++)
                As[s][h * 8 + i][r] = to_tf32(fast_tanh(v[i] + u[i]));
        }

        // ---- prefetch A(ch+1) into regs (latency hidden under mma) ----
        if (ch + 1 < NCH) {
            const int k0n = (ch + 1) * BK;
            as0 = *reinterpret_cast<const float4*>(sp + k0n);
            as1 = *reinterpret_cast<const float4*>(sp + k0n + 4);
            at0 = *reinterpret_cast<const float4*>(tp + k0n);
            at1 = *reinterpret_cast<const float4*>(tp + k0n + 4);
        }

        asm volatile("cp.async.wait_group 0;" ::: "memory");   // B(ch) landed
        __syncthreads();

        // ---- issue cp.async B(ch+1) -> other buffer ----
        if (ch + 1 < NCH) {
            const float* wsrc = wp + (ch + 1) * BK;
            uint32_t dst = (s ? bs_dst0 : bs_dst1);
            asm volatile(
                "cp.async.cg.shared.global [%0], [%1], 16;\n"
                "cp.async.cg.shared.global [%2], [%3], 16;\n"
                "cp.async.commit_group;"
                :: "r"(dst), "l"(wsrc), "r"(dst + 16), "l"(wsrc + 4) : "memory");
        }

        // ---- mma over buf s: 2 k-steps of 8 ----
#pragma unroll
        for (int ks = 0; ks < 2; ks++) {
            const int kb = ks * 8;
            uint32_t a[4][4];
#pragma unroll
            for (int mt = 0; mt < 4; mt++) {
                const int mr = wm * 64 + mt * 16 + g;
                a[mt][0] = __float_as_uint(As[s][kb + c][mr]);
                a[mt][1] = __float_as_uint(As[s][kb + c][mr + 8]);
                a[mt][2] = __float_as_uint(As[s][kb + c + 4][mr]);
                a[mt][3] = __float_as_uint(As[s][kb + c + 4][mr + 8]);
            }
#pragma unroll
            for (int nt = 0; nt < 4; nt++) {
                const int nn = wn * 32 + nt * 8 + g;
                uint32_t b0 = __float_as_uint(to_tf32(Bs[s][nn][kb + c]));
                uint32_t b1 = __float_as_uint(to_tf32(Bs[s][nn][kb + c + 4]));
#pragma unroll
                for (int mt = 0; mt < 4; mt++)
                    mma_tf32(acc[mt][nt], a[mt], b0, b1);
            }
        }
    }

    // ---- epilogue: bias + store (float2 per fragment half) ----
#pragma unroll
    for (int nt = 0; nt < 4; nt++) {
        const int col = n0 + wn * 32 + nt * 8 + 2 * c;
        const float2 bz = *reinterpret_cast<const float2*>(bias + col);
#pragma unroll
        for (int mt = 0; mt < 4; mt++) {
            const long long row = m0 + wm * 64 + mt * 16 + g;
            float2 o1, o2;
            o1.x = acc[mt][nt][0] + bz.x;
            o1.y = acc[mt][nt][1] + bz.y;
            o2.x = acc[mt][nt][2] + bz.x;
            o2.y = acc[mt][nt][3] + bz.y;
            *reinterpret_cast<float2*>(out + (size_t)row * Vv + col) = o1;
            *reinterpret_cast<float2*>(out + (size_t)(row + 8) * Vv + col) = o2;
        }
    }
}

// Defensive tail: if the harness packs the tuple (output, source_lengths,
// target_lengths) into one float buffer, append the lengths cast to float.
__global__ void joiner_tail_kernel(const int* __restrict__ src_len,
                                   const int* __restrict__ tgt_len,
                                   float* __restrict__ out, int extras) {
    int i = threadIdx.x;
    if (i < extras) {
        size_t base = (size_t)Mm * Vv;
        if (i < Bb) out[base + i] = (float)src_len[i];
        else if (i < 2 * Bb) out[base + i] = (float)tgt_len[i - Bb];
        else out[base + i] = 0.0f;
    }
}

extern "C" void kernel_launch(void* const* d_in, const int* in_sizes, int n_in,
                              void* d_out, int out_size) {
    const float* src     = (const float*)d_in[0];
    const int*   src_len = (const int*)d_in[1];
    const float* tgt     = (const float*)d_in[2];
    const int*   tgt_len = (const int*)d_in[3];
    const float* W       = (const float*)d_in[4];
    const float* bias    = (const float*)d_in[5];
    float* out = (float*)d_out;

    dim3 grid((unsigned)(Mm / BM), Vv / BN);   // 1250 x 8
    joiner_mma_kernel<<<grid, 256>>>(src, tgt, W, bias, out);

    long long extras = (long long)out_size - (long long)Mm * Vv;
    if (extras > 0) {
        int e = (int)(extras > 64 ? 64 : extras);
        joiner_tail_kernel<<<1, 64>>>(src_len, tgt_len, out, e);
    }
}

// round 5
// speedup vs baseline: 5.0883x; 1.8824x over previous
#include <cuda_runtime.h>
#include <cuda_fp16.h>
#include <cstdint>

// RNN-T Joiner, fp16 tensor-core path (baseline PTX only; tcgen05 blocked by
// compute_103 lowering).
//   Phase 1: A_half[m,k] = fp16(tanh(src+tgt)), W -> fp16
//   Phase 2: pure fp16 GEMM m16n8k16, fp32 accum, 4-stage cp.async pipeline.
// M = 160000, K = 512, N = 1024.

constexpr int Bb = 4, Tt = 400, Uu = 100, Dd = 512, Vv = 1024;
constexpr long long Mm = (long long)Bb * Tt * Uu;   // 160000 = 128*1250

#define BM 128
#define BN 128
#define BK 32
#define NCH (Dd / BK)        // 16
#define STG 4                // cp.async stages
#define RSTRIDE 40           // smem row stride in halfs (80B): conflict-free

// Scratch (static device globals are the sanctioned scratch mechanism).
__device__ __half A_half[(size_t)Mm * Dd];   // 164 MB
__device__ __half W_half[(size_t)Vv * Dd];   // 1 MB

__device__ __forceinline__ float fast_tanh(float x) {
    float y; asm("tanh.approx.f32 %0, %1;" : "=f"(y) : "f"(x)); return y;
}
__device__ __forceinline__ uint32_t smem_u32(const void* p) {
    uint32_t a;
    asm("{ .reg .u64 t; cvta.to.shared.u64 t, %1; cvt.u32.u64 %0, t; }" : "=r"(a) : "l"(p));
    return a;
}

// ---------------- Phase 1a: A = fp16(tanh(src + tgt)) ----------------
__global__ __launch_bounds__(256)
void prep_a_kernel(const float* __restrict__ src, const float* __restrict__ tgt) {
    size_t idx = (size_t)blockIdx.x * 256 + threadIdx.x;   // one per 8 elems
    int m = (int)(idx >> 6);
    int kv = ((int)idx & 63) * 8;
    int b = m / (Tt * Uu);
    int rem = m - b * (Tt * Uu);
    int t = rem / Uu;
    int u = rem - t * Uu;
    const float* sp = src + ((size_t)b * Tt + t) * Dd + kv;
    const float* tp = tgt + ((size_t)b * Uu + u) * Dd + kv;
    float4 s0 = *reinterpret_cast<const float4*>(sp);
    float4 s1 = *reinterpret_cast<const float4*>(sp + 4);
    float4 t0 = *reinterpret_cast<const float4*>(tp);
    float4 t1 = *reinterpret_cast<const float4*>(tp + 4);
    __half2 h[4];
    h[0] = __floats2half2_rn(fast_tanh(s0.x + t0.x), fast_tanh(s0.y + t0.y));
    h[1] = __floats2half2_rn(fast_tanh(s0.z + t0.z), fast_tanh(s0.w + t0.w));
    h[2] = __floats2half2_rn(fast_tanh(s1.x + t1.x), fast_tanh(s1.y + t1.y));
    h[3] = __floats2half2_rn(fast_tanh(s1.z + t1.z), fast_tanh(s1.w + t1.w));
    *reinterpret_cast<uint4*>(&A_half[(size_t)m * Dd + kv]) =
        *reinterpret_cast<uint4*>(h);
}

// ---------------- Phase 1b: W -> fp16 ----------------
__global__ __launch_bounds__(256)
void prep_w_kernel(const float* __restrict__ W) {
    size_t idx = ((size_t)blockIdx.x * 256 + threadIdx.x) * 8;
    float4 w0 = *reinterpret_cast<const float4*>(W + idx);
    float4 w1 = *reinterpret_cast<const float4*>(W + idx + 4);
    __half2 h[4];
    h[0] = __floats2half2_rn(w0.x, w0.y);
    h[1] = __floats2half2_rn(w0.z, w0.w);
    h[2] = __floats2half2_rn(w1.x, w1.y);
    h[3] = __floats2half2_rn(w1.z, w1.w);
    *reinterpret_cast<uint4*>(&W_half[idx]) = *reinterpret_cast<uint4*>(h);
}

// ---------------- Phase 2: fp16 GEMM ----------------
__device__ __forceinline__ void mma_fp16(float* d, const uint32_t* a,
                                         uint32_t b0, uint32_t b1) {
    asm volatile(
        "mma.sync.aligned.m16n8k16.row.col.f32.f16.f16.f32 "
        "{%0,%1,%2,%3}, {%4,%5,%6,%7}, {%8,%9}, {%0,%1,%2,%3};"
        : "+f"(d[0]), "+f"(d[1]), "+f"(d[2]), "+f"(d[3])
        : "r"(a[0]), "r"(a[1]), "r"(a[2]), "r"(a[3]), "r"(b0), "r"(b1));
}

constexpr int STAGE_H = BM * RSTRIDE;          // halfs per stage (5120)
constexpr int SMEM_TOTAL = 2 * STG * STAGE_H * 2;   // A + B, bytes = 81920

__global__ __launch_bounds__(256, 2)
void joiner_gemm_fp16(const float* __restrict__ bias, float* __restrict__ out) {
    extern __shared__ __half sm[];
    __half* Asm = sm;
    __half* Bsm = sm + STG * STAGE_H;

    const int tid = threadIdx.x;
    const int wid = tid >> 5, lid = tid & 31;
    const int g = lid >> 2, c = lid & 3;
    const int wm = wid >> 2, wn = wid & 3;        // warp grid 2(m) x 4(n)
    const size_t m0 = (size_t)blockIdx.x * BM;
    const int n0 = blockIdx.y * BN;

    // producer mapping: 2 threads per row, 16 halfs (32B) each
    const int r = tid >> 1;
    const int h = tid & 1;
    const __half* agp = A_half + (m0 + r) * Dd + h * 16;
    const __half* bgp = W_half + (size_t)(n0 + r) * Dd + h * 16;
    const uint32_t a_dst0 = smem_u32(Asm) + (uint32_t)(r * 80 + h * 32);
    const uint32_t b_dst0 = smem_u32(Bsm) + (uint32_t)(r * 80 + h * 32);

    float acc[4][4][4];
#pragma unroll
    for (int mt = 0; mt < 4; mt++)
#pragma unroll
        for (int nt = 0; nt < 4; nt++)
#pragma unroll
            for (int i = 0; i < 4; i++) acc[mt][nt][i] = 0.0f;

#define ISSUE_STAGE(CH) do {                                                    \
        int st_ = (CH) & (STG - 1);                                             \
        const __half* ag_ = agp + (CH) * BK;                                    \
        const __half* bg_ = bgp + (CH) * BK;                                    \
        uint32_t ad_ = a_dst0 + st_ * (STAGE_H * 2);                            \
        uint32_t bd_ = b_dst0 + st_ * (STAGE_H * 2);                            \
        asm volatile(                                                           \
            "cp.async.cg.shared.global [%0], [%1], 16;\n"                       \
            "cp.async.cg.shared.global [%2], [%3], 16;\n"                       \
            "cp.async.cg.shared.global [%4], [%5], 16;\n"                       \
            "cp.async.cg.shared.global [%6], [%7], 16;\n"                       \
            "cp.async.commit_group;"                                            \
            :: "r"(ad_), "l"(ag_), "r"(ad_ + 16), "l"(ag_ + 8),                 \
               "r"(bd_), "l"(bg_), "r"(bd_ + 16), "l"(bg_ + 8) : "memory");     \
    } while (0)

    ISSUE_STAGE(0); ISSUE_STAGE(1); ISSUE_STAGE(2);

    for (int ch = 0; ch < NCH; ch++) {
        const int rem = NCH - 1 - ch;
        if (rem >= 2)      asm volatile("cp.async.wait_group 2;" ::: "memory");
        else if (rem == 1) asm volatile("cp.async.wait_group 1;" ::: "memory");
        else               asm volatile("cp.async.wait_group 0;" ::: "memory");
        __syncthreads();
        if (ch + 3 < NCH) ISSUE_STAGE(ch + 3);

        const __half* a_st = Asm + (ch & (STG - 1)) * STAGE_H;
        const __half* b_st = Bsm + (ch & (STG - 1)) * STAGE_H;
#pragma unroll
        for (int ks = 0; ks < 2; ks++) {
            const int kb = ks * 16;
            uint32_t a[4][4];
#pragma unroll
            for (int mt = 0; mt < 4; mt++) {
                const int mr = wm * 64 + mt * 16 + g;
                a[mt][0] = *reinterpret_cast<const uint32_t*>(&a_st[mr * RSTRIDE + kb + 2 * c]);
                a[mt][1] = *reinterpret_cast<const uint32_t*>(&a_st[(mr + 8) * RSTRIDE + kb + 2 * c]);
                a[mt][2] = *reinterpret_cast<const uint32_t*>(&a_st[mr * RSTRIDE + kb + 2 * c + 8]);
                a[mt][3] = *reinterpret_cast<const uint32_t*>(&a_st[(mr + 8) * RSTRIDE + kb + 2 * c + 8]);
            }
#pragma unroll
            for (int nt = 0; nt < 4; nt++) {
                const int nn = wn * 32 + nt * 8 + g;
                uint32_t b0 = *reinterpret_cast<const uint32_t*>(&b_st[nn * RSTRIDE + kb + 2 * c]);
                uint32_t b1 = *reinterpret_cast<const uint32_t*>(&b_st[nn * RSTRIDE + kb + 2 * c + 8]);
#pragma unroll
                for (int mt = 0; mt < 4; mt++)
                    mma_fp16(acc[mt][nt], a[mt], b0, b1);
            }
        }
    }

    // epilogue: bias + float2 stores
#pragma unroll
    for (int nt = 0; nt < 4; nt++) {
        const int col = n0 + wn * 32 + nt * 8 + 2 * c;
        const float2 bz = *reinterpret_cast<const float2*>(bias + col);
#pragma unroll
        for (int mt = 0; mt < 4; mt++) {
            const size_t row = m0 + wm * 64 + mt * 16 + g;
            float2 o1, o2;
            o1.x = acc[mt][nt][0] + bz.x;
            o1.y = acc[mt][nt][1] + bz.y;
            o2.x = acc[mt][nt][2] + bz.x;
            o2.y = acc[mt][nt][3] + bz.y;
            *reinterpret_cast<float2*>(out + row * Vv + col) = o1;
            *reinterpret_cast<float2*>(out + (row + 8) * Vv + col) = o2;
        }
    }
}

// Defensive tail: append lengths if harness packs the whole tuple.
__global__ void joiner_tail_kernel(const int* __restrict__ src_len,
                                   const int* __restrict__ tgt_len,
                                   float* __restrict__ out, int extras) {
    int i = threadIdx.x;
    if (i < extras) {
        size_t base = (size_t)Mm * Vv;
        if (i < Bb) out[base + i] = (float)src_len[i];
        else if (i < 2 * Bb) out[base + i] = (float)tgt_len[i - Bb];
        else out[base + i] = 0.0f;
    }
}

extern "C" void kernel_launch(void* const* d_in, const int* in_sizes, int n_in,
                              void* d_out, int out_size) {
    const float* src     = (const float*)d_in[0];
    const int*   src_len = (const int*)d_in[1];
    const float* tgt     = (const float*)d_in[2];
    const int*   tgt_len = (const int*)d_in[3];
    const float* W       = (const float*)d_in[4];
    const float* bias    = (const float*)d_in[5];
    float* out = (float*)d_out;

    // Phase 1: materialize fp16 operands
    prep_a_kernel<<<(unsigned)(Mm * (Dd / 8) / 256), 256>>>(src, tgt);   // 40000 blocks
    prep_w_kernel<<<(Vv * Dd / 8) / 256, 256>>>(W);                       // 256 blocks

    // Phase 2: GEMM
    cudaFuncSetAttribute(joiner_gemm_fp16,
                         cudaFuncAttributeMaxDynamicSharedMemorySize, SMEM_TOTAL);
    dim3 grid((unsigned)(Mm / BM), Vv / BN);   // 1250 x 8
    joiner_gemm_fp16<<<grid, 256, SMEM_TOTAL>>>(bias, out);

    long long extras = (long long)out_size - (long long)Mm * Vv;
    if (extras > 0) {
        int e = (int)(extras > 64 ? 64 : extras);
        joiner_tail_kernel<<<1, 64>>>(src_len, tgt_len, out, e);
    }
}